// round 3
// baseline (speedup 1.0000x reference)
#include <cuda_runtime.h>
#include <cuda_bf16.h>

// QuantumKANRegressor on sm_100a — batch-packed f32x2 layout.
// Lane l handles rows (2l, 2l+1) packed; warp w iterates features w, w+8, ..., w+56.
// Weights are warp-uniform -> broadcast LDS from pre-packed shared (zero reg cost).
// Sign-absorbed Chebyshev recurrence: B_{d+1} = (+-2x) B_d + B_{d-1} gives
// B_d = s_d T_d, s_d = (d&2)?-1:+1; s_d (and 1/sum|w|) folded into staged weights.

#define F_DIM   64
#define DEG     16
#define KC      6          // KAN_DEG + 1
#define THREADS 256
#define WARPS   8
#define RB      64         // rows per block
#define B_TOTAL 65536

typedef unsigned long long u64;

static __device__ __forceinline__ u64 pk(float lo, float hi) {
    u64 r; asm("mov.b64 %0, {%1, %2};" : "=l"(r) : "f"(lo), "f"(hi)); return r;
}
static __device__ __forceinline__ void upk(u64 v, float& lo, float& hi) {
    asm("mov.b64 {%0, %1}, %2;" : "=f"(lo), "=f"(hi) : "l"(v));
}
static __device__ __forceinline__ u64 fma2(u64 a, u64 b, u64 c) {
    u64 d; asm("fma.rn.f32x2 %0, %1, %2, %3;" : "=l"(d) : "l"(a), "l"(b), "l"(c)); return d;
}
static __device__ __forceinline__ u64 mul2(u64 a, u64 b) {
    u64 d; asm("mul.rn.f32x2 %0, %1, %2;" : "=l"(d) : "l"(a), "l"(b)); return d;
}
static __device__ __forceinline__ u64 add2(u64 a, u64 b) {
    u64 d; asm("add.rn.f32x2 %0, %1, %2;" : "=l"(d) : "l"(a), "l"(b)); return d;
}
static __device__ __forceinline__ float tanh_fast(float f) {
    // tanh(f) = 1 - 2/(exp(2f)+1); |f| <= 1 here.
    float e = __expf(2.0f * f);
    return 1.0f - __fdividef(2.0f, e + 1.0f);
}

__global__ void __launch_bounds__(THREADS)
qkan3_kernel(const float* __restrict__ X,
             const float* __restrict__ W,     // [64][16]
             const float* __restrict__ C,     // [64][6]
             float* __restrict__ out)
{
    __shared__ float xs[RB][F_DIM + 1];      // +1 pad: 2-way max conflict on reads
    __shared__ u64   wp[F_DIM][DEG];         // packed (w',w'), sign & 1/den folded
    __shared__ u64   cp[F_DIM][KC];          // packed (c',c'), sign folded
    __shared__ float red[WARPS][RB];

    const int tid  = threadIdx.x;
    const int lane = tid & 31;
    const int warp = tid >> 5;
    const int row0 = blockIdx.x * RB;

    // ---- stage X tile (coalesced float4) ----
    {
        const float4* Xv = (const float4*)(X + (size_t)row0 * F_DIM);
        #pragma unroll
        for (int i = 0; i < (RB * F_DIM / 4) / THREADS; i++) {
            int t = tid + i * THREADS;            // float4 index
            float4 v = Xv[t];
            int row = t >> 4;
            int col = (t & 15) << 2;
            xs[row][col]     = v.x;
            xs[row][col + 1] = v.y;
            xs[row][col + 2] = v.z;
            xs[row][col + 3] = v.w;
        }
    }
    // ---- stage weights, pre-packed, signs and 1/den folded ----
    if (tid < F_DIM) {
        const int f = tid;
        float wl[DEG];
        float den = 0.0f;
        const float4* Wv = (const float4*)(W + f * DEG);
        #pragma unroll
        for (int q = 0; q < DEG / 4; q++) {
            float4 v = Wv[q];
            wl[q*4+0] = v.x; wl[q*4+1] = v.y; wl[q*4+2] = v.z; wl[q*4+3] = v.w;
        }
        #pragma unroll
        for (int d = 0; d < DEG; d++) den += fabsf(wl[d]);
        const float inv = 1.0f / den;
        #pragma unroll
        for (int d = 0; d < DEG; d++) {
            float s = ((d + 1) & 2) ? -inv : inv;   // weight d multiplies T_{d+1}
            float v = wl[d] * s;
            wp[f][d] = pk(v, v);
        }
        #pragma unroll
        for (int k = 0; k < KC; k++) {
            float s = (k & 2) ? -1.0f : 1.0f;
            float v = C[f * KC + k] * s;
            cp[f][k] = pk(v, v);
        }
    }
    __syncthreads();

    // ---- preload this lane's 8 packed row-pairs (one per feature iteration) ----
    u64 xp[8];
    #pragma unroll
    for (int i = 0; i < 8; i++) {
        const int f = warp + (i << 3);
        xp[i] = pk(xs[2 * lane][f], xs[2 * lane + 1][f]);
    }

    const u64 ONE2 = 0x3f8000003f800000ULL;   // (1.0f, 1.0f)
    const u64 NEG2 = 0xc0000000c0000000ULL;   // (-2.0f, -2.0f)

    u64 acc2 = 0ULL;                          // packed (0.0f, 0.0f)

    #pragma unroll 2
    for (int i = 0; i < 8; i++) {
        const int f = warp + (i << 3);        // warp-uniform feature index
        const u64 x   = xp[i];
        const u64 x2  = add2(x, x);
        const u64 nx2 = mul2(x, NEG2);

        // QSVT: a = sum_{d=1..16} w'_d B_d(x)   (== feat, 1/den folded)
        u64 Bp = ONE2;                        // B_0
        u64 Bc = x;                           // B_1
        u64 a  = mul2(wp[f][0], Bc);
        #pragma unroll
        for (int d = 1; d < DEG; d++) {
            u64 Bn = fma2((d & 1) ? nx2 : x2, Bc, Bp);   // B_{d+1}
            a = fma2(wp[f][d], Bn, a);
            Bp = Bc; Bc = Bn;
        }

        float f0, f1; upk(a, f0, f1);
        const u64 z   = pk(tanh_fast(f0), tanh_fast(f1));
        const u64 z2  = add2(z, z);
        const u64 nz2 = mul2(z, NEG2);

        // KAN: o = sum_{k=0..5} c'_k B_k(z)
        u64 Kp = ONE2;
        u64 Kc = z;
        u64 o  = fma2(cp[f][1], z, cp[f][0]);
        #pragma unroll
        for (int k = 1; k < KC - 1; k++) {
            u64 Kn = fma2((k & 1) ? nz2 : z2, Kc, Kp);
            o = fma2(cp[f][k + 1], Kn, o);
            Kp = Kc; Kc = Kn;
        }
        acc2 = add2(acc2, o);
    }

    // ---- reduce 8 warp-partials per row in shared ----
    float a0, a1; upk(acc2, a0, a1);
    red[warp][2 * lane]     = a0;
    red[warp][2 * lane + 1] = a1;
    __syncthreads();

    if (tid < RB) {
        float s = 0.0f;
        #pragma unroll
        for (int w = 0; w < WARPS; w++) s += red[w][tid];
        out[row0 + tid] = s;
    }
}

extern "C" void kernel_launch(void* const* d_in, const int* in_sizes, int n_in,
                              void* d_out, int out_size) {
    const float* X = (const float*)d_in[0];
    const float* W = (const float*)d_in[1];
    const float* C = (const float*)d_in[2];
    float* out = (float*)d_out;

    const int grid = B_TOTAL / RB;            // 1024
    qkan3_kernel<<<grid, THREADS>>>(X, W, C, out);
}